// round 1
// baseline (speedup 1.0000x reference)
#include <cuda_runtime.h>
#include <cstdint>

// Problem constants
#define BATCH 16
#define CH    16
#define FIL   32
#define IMH   256
#define IMW   256

// Tiling
#define TH 16        // output tile height
#define TW 32        // output tile width
#define HALO_H 18    // TH + 2
#define HALO_W 34    // TW + 2
#define SROW 35      // padded smem row stride (floats) -> conflict-free LDS
#define NTHREADS 256

typedef unsigned long long u64;

// smem layout: [ CH * HALO_H * SROW floats input tile ][ 144*32 u64 packed weights ]
#define SMEM_IN_FLOATS (CH * HALO_H * SROW)              // 10080 floats
#define SMEM_BYTES (SMEM_IN_FLOATS * 4 + CH * 9 * FIL * 8) // 40320 + 36864 = 77184

__device__ __forceinline__ u64 pack2(float lo, float hi) {
    u64 r;
    asm("mov.b64 %0, {%1, %2};" : "=l"(r) : "f"(lo), "f"(hi));
    return r;
}
__device__ __forceinline__ void unpack2(u64 v, float& lo, float& hi) {
    asm("mov.b64 {%0, %1}, %2;" : "=f"(lo), "=f"(hi) : "l"(v));
}
// packed dual fp32 FMA: d = a*b + c  (elementwise on {lo,hi}) — sm_100+/sm_103a
__device__ __forceinline__ u64 ffma2(u64 a, u64 b, u64 c) {
    u64 d;
    asm("fma.rn.f32x2 %0, %1, %2, %3;" : "=l"(d) : "l"(a), "l"(b), "l"(c));
    return d;
}

extern __shared__ float smem[];

__global__ __launch_bounds__(NTHREADS, 2)
void conv3x3_sigmoid_kernel(const float* __restrict__ x,
                            const float* __restrict__ wgt,
                            const float* __restrict__ bias,
                            float* __restrict__ out) {
    float* s_in = smem;                               // [CH][HALO_H][SROW]
    u64*   s_w  = (u64*)(smem + SMEM_IN_FLOATS);      // [144][32], each = {w,w}

    const int tid = threadIdx.x;
    const int b   = blockIdx.z;
    const int h0  = blockIdx.y * TH;
    const int w0  = blockIdx.x * TW;

    // ---- Load weights, duplicated into f32x2 lanes ----
    // wgt layout: (c*9 + kh*3 + kw) * 32 + f
    for (int i = tid; i < CH * 9 * FIL; i += NTHREADS) {
        float w = wgt[i];
        s_w[i] = pack2(w, w);
    }

    // ---- Load input halo tile (zero-padded borders) ----
    const int total_in = CH * HALO_H * HALO_W;        // 9792
    for (int i = tid; i < total_in; i += NTHREADS) {
        int c   = i / (HALO_H * HALO_W);
        int rem = i - c * (HALO_H * HALO_W);
        int row = rem / HALO_W;
        int col = rem - row * HALO_W;
        int gh = h0 - 1 + row;
        int gw = w0 - 1 + col;
        float v = 0.0f;
        if (gh >= 0 && gh < IMH && gw >= 0 && gw < IMW)
            v = x[((b * CH + c) * IMH + gh) * IMW + gw];
        s_in[(c * HALO_H + row) * SROW + col] = v;
    }
    __syncthreads();

    // ---- Thread mapping ----
    // fg uniform within a warp (tid>>6) so weight LDS is a broadcast.
    const int fg = tid >> 6;          // filter group: 8 filters each, 0..3
    const int pg = tid & 63;          // pixel group
    const int r  = pg >> 2;           // output row within tile, 0..15
    const int ws = pg & 3;            // 8-wide w segment, 0..3

    // 32 packed accumulators: 4 pixel-pairs x 8 filters = 8 pixels x 8 filters
    u64 acc[4][8];
    #pragma unroll
    for (int t = 0; t < 4; ++t)
        #pragma unroll
        for (int f = 0; f < 8; ++f)
            acc[t][f] = 0ull;   // bit pattern {0.f, 0.f}

    for (int c = 0; c < CH; ++c) {
        #pragma unroll
        for (int kh = 0; kh < 3; ++kh) {
            const float* rowp = s_in + (c * HALO_H + r + kh) * SROW + ws * 8;
            float xv[10];
            #pragma unroll
            for (int j = 0; j < 10; ++j) xv[j] = rowp[j];

            // pixel pairs, shifted variants for the 3 kw taps
            u64 xp0[5], xp1[4];
            #pragma unroll
            for (int t = 0; t < 5; ++t) xp0[t] = pack2(xv[2*t],   xv[2*t+1]);
            #pragma unroll
            for (int t = 0; t < 4; ++t) xp1[t] = pack2(xv[2*t+1], xv[2*t+2]);

            const u64* wbase = s_w + (c * 9 + kh * 3) * FIL + fg * 8;
            #pragma unroll
            for (int kw = 0; kw < 3; ++kw) {
                u64 wp[8];
                #pragma unroll
                for (int f = 0; f < 8; ++f) wp[f] = wbase[kw * FIL + f];
                #pragma unroll
                for (int t = 0; t < 4; ++t) {
                    u64 xpv = (kw == 0) ? xp0[t] : (kw == 1) ? xp1[t] : xp0[t + 1];
                    #pragma unroll
                    for (int f = 0; f < 8; ++f)
                        acc[t][f] = ffma2(xpv, wp[f], acc[t][f]);
                }
            }
        }
    }

    // ---- Epilogue: + bias, sigmoid, store (float4) ----
    const int h     = h0 + r;
    const int wout0 = w0 + ws * 8;   // multiple of 8 -> 16B aligned
    #pragma unroll
    for (int f = 0; f < 8; ++f) {
        const int Fo = fg * 8 + f;
        float v[8];
        #pragma unroll
        for (int t = 0; t < 4; ++t) unpack2(acc[t][f], v[2*t], v[2*t+1]);

        const float* bp = bias + (Fo * IMH + h) * IMW + wout0;
        float4 bb0 = *(const float4*)(bp);
        float4 bb1 = *(const float4*)(bp + 4);
        v[0] += bb0.x; v[1] += bb0.y; v[2] += bb0.z; v[3] += bb0.w;
        v[4] += bb1.x; v[5] += bb1.y; v[6] += bb1.z; v[7] += bb1.w;

        #pragma unroll
        for (int i = 0; i < 8; ++i)
            v[i] = 1.0f / (1.0f + __expf(-v[i]));

        float* op = out + (((size_t)b * FIL + Fo) * IMH + h) * IMW + wout0;
        float4 o0 = {v[0], v[1], v[2], v[3]};
        float4 o1 = {v[4], v[5], v[6], v[7]};
        *(float4*)(op)     = o0;
        *(float4*)(op + 4) = o1;
    }
}

extern "C" void kernel_launch(void* const* d_in, const int* in_sizes, int n_in,
                              void* d_out, int out_size) {
    const float* x    = (const float*)d_in[0];
    const float* wgt  = (const float*)d_in[1];
    const float* bias = (const float*)d_in[2];
    float* out = (float*)d_out;

    cudaFuncSetAttribute(conv3x3_sigmoid_kernel,
                         cudaFuncAttributeMaxDynamicSharedMemorySize, SMEM_BYTES);

    dim3 grid(IMW / TW, IMH / TH, BATCH);   // (8, 16, 16)
    conv3x3_sigmoid_kernel<<<grid, NTHREADS, SMEM_BYTES>>>(x, wgt, bias, out);
}

// round 3
// speedup vs baseline: 1.3567x; 1.3567x over previous
#include <cuda_runtime.h>
#include <cstdint>

// Problem constants
#define BATCH 16
#define CH    16
#define FIL   32
#define IMH   256
#define IMW   256

// Tiling: 8 x 32 output tile per CTA
#define TH 8
#define TW 32
#define HALO_H 10        // TH + 2
#define HALO_W 34        // TW + 2
#define SROW2  38        // u64 row stride for duplicated input (16B-aligned, conflict-free)
#define NTHREADS 256

typedef unsigned long long u64;

#define SMEM_IN_U64 (CH * HALO_H * SROW2)     // 6080 u64
#define SMEM_W_U64  (CH * 9 * (FIL / 2))      // 2304 u64 (filter pairs, natural layout)
#define SMEM_BYTES  ((SMEM_IN_U64 + SMEM_W_U64) * 8)   // 67072 B -> 3 CTAs/SM

__device__ __forceinline__ u64 pack2(float lo, float hi) {
    u64 r;
    asm("mov.b64 %0, {%1, %2};" : "=l"(r) : "f"(lo), "f"(hi));
    return r;
}
__device__ __forceinline__ void unpack2(u64 v, float& lo, float& hi) {
    asm("mov.b64 {%0, %1}, %2;" : "=f"(lo), "=f"(hi) : "l"(v));
}
// packed dual fp32 FMA (sm_103a): d.lo = a.lo*b.lo + c.lo ; d.hi likewise
__device__ __forceinline__ u64 ffma2(u64 a, u64 b, u64 c) {
    u64 d;
    asm("fma.rn.f32x2 %0, %1, %2, %3;" : "=l"(d) : "l"(a), "l"(b), "l"(c));
    return d;
}

extern __shared__ u64 smem64[];

__global__ __launch_bounds__(NTHREADS, 3)
void conv3x3_sigmoid_v2(const float* __restrict__ x,
                        const float* __restrict__ wgt,
                        const float* __restrict__ bias,
                        float* __restrict__ out) {
    u64* s_in = smem64;                 // [CH][HALO_H][SROW2], each = {x,x}
    u64* s_w  = smem64 + SMEM_IN_U64;   // [CH*9][16] filter pairs {w_{2f}, w_{2f+1}}

    const int tid = threadIdx.x;
    const int b   = blockIdx.z;
    const int h0  = blockIdx.y * TH;
    const int w0  = blockIdx.x * TW;

    // ---- Weights: filter pairs are contiguous in gmem -> straight u64 copy ----
    const u64* wg64 = (const u64*)wgt;
    #pragma unroll
    for (int i = tid; i < SMEM_W_U64; i += NTHREADS)
        s_w[i] = wg64[i];

    // ---- Input halo tile, duplicated {x,x} (zero-padded borders) ----
    const int total_in = CH * HALO_H * HALO_W;    // 5440
    for (int i = tid; i < total_in; i += NTHREADS) {
        int c   = i / (HALO_H * HALO_W);
        int rem = i - c * (HALO_H * HALO_W);
        int row = rem / HALO_W;
        int col = rem - row * HALO_W;
        int gh = h0 - 1 + row;
        int gw = w0 - 1 + col;
        float v = 0.0f;
        if (gh >= 0 && gh < IMH && gw >= 0 && gw < IMW)
            v = x[((b * CH + c) * IMH + gh) * IMW + gw];
        s_in[(c * HALO_H + row) * SROW2 + col] = pack2(v, v);
    }
    __syncthreads();

    // ---- Thread mapping ----
    // fg = tid>>5: uniform within a warp -> weight LDS.64 is a broadcast.
    // Within an 8-thread LDS phase, r spans 0..7 -> conflict-free x LDS.128.
    const int fg = tid >> 5;         // filter group (4 filters = 2 pairs), 0..7
    const int pg = tid & 31;
    const int r  = pg & 7;           // output row in tile
    const int ws = pg >> 3;          // 8-wide pixel segment, 0..3

    // acc[p][q]: pixel p (0..7), filter-pair q (0..1) -> 8 px x 4 filters
    u64 acc[8][2];
    #pragma unroll
    for (int p = 0; p < 8; ++p) { acc[p][0] = 0ull; acc[p][1] = 0ull; }

    #pragma unroll 1
    for (int c = 0; c < CH; ++c) {
        #pragma unroll
        for (int kh = 0; kh < 3; ++kh) {
            const ulonglong2* rp = (const ulonglong2*)
                (s_in + (c * HALO_H + r + kh) * SROW2 + ws * 8);
            u64 xp[10];
            #pragma unroll
            for (int t = 0; t < 5; ++t) {
                ulonglong2 v = rp[t];    // LDS.128, 16B aligned
                xp[2 * t]     = v.x;
                xp[2 * t + 1] = v.y;
            }

            const u64* wk = s_w + (c * 9 + kh * 3) * (FIL / 2) + fg * 2;
            u64 w[3][2];
            #pragma unroll
            for (int kw = 0; kw < 3; ++kw) {
                w[kw][0] = wk[kw * (FIL / 2)];
                w[kw][1] = wk[kw * (FIL / 2) + 1];
            }

            #pragma unroll
            for (int kw = 0; kw < 3; ++kw)
                #pragma unroll
                for (int p = 0; p < 8; ++p) {
                    acc[p][0] = ffma2(xp[p + kw], w[kw][0], acc[p][0]);
                    acc[p][1] = ffma2(xp[p + kw], w[kw][1], acc[p][1]);
                }
        }
    }

    // ---- Epilogue: +bias, sigmoid, store ----
    const int h  = h0 + r;
    const int wc = w0 + ws * 8;      // multiple of 8 -> 16B aligned
    #pragma unroll
    for (int q = 0; q < 2; ++q) {
        float a0[8], a1[8];
        #pragma unroll
        for (int p = 0; p < 8; ++p) unpack2(acc[p][q], a0[p], a1[p]);

        const int f0 = fg * 4 + 2 * q;
        #pragma unroll
        for (int half = 0; half < 2; ++half) {
            const float* av = half ? a1 : a0;
            const int f = f0 + half;

            const float* bp = bias + (f * IMH + h) * IMW + wc;
            float4 bb0 = *(const float4*)(bp);
            float4 bb1 = *(const float4*)(bp + 4);
            float v[8];
            v[0] = av[0] + bb0.x; v[1] = av[1] + bb0.y;
            v[2] = av[2] + bb0.z; v[3] = av[3] + bb0.w;
            v[4] = av[4] + bb1.x; v[5] = av[5] + bb1.y;
            v[6] = av[6] + bb1.z; v[7] = av[7] + bb1.w;
            #pragma unroll
            for (int i = 0; i < 8; ++i)
                v[i] = 1.0f / (1.0f + __expf(-v[i]));

            float* op = out + (((size_t)b * FIL + f) * IMH + h) * IMW + wc;
            *(float4*)(op)     = make_float4(v[0], v[1], v[2], v[3]);
            *(float4*)(op + 4) = make_float4(v[4], v[5], v[6], v[7]);
        }
    }
}

extern "C" void kernel_launch(void* const* d_in, const int* in_sizes, int n_in,
                              void* d_out, int out_size) {
    const float* x    = (const float*)d_in[0];
    const float* wgt  = (const float*)d_in[1];
    const float* bias = (const float*)d_in[2];
    float* out = (float*)d_out;

    cudaFuncSetAttribute(conv3x3_sigmoid_v2,
                         cudaFuncAttributeMaxDynamicSharedMemorySize, SMEM_BYTES);

    dim3 grid(IMW / TW, IMH / TH, BATCH);   // (8, 32, 16) = 4096 CTAs
    conv3x3_sigmoid_v2<<<grid, NTHREADS, SMEM_BYTES>>>(x, wgt, bias, out);
}